// round 12
// baseline (speedup 1.0000x reference)
#include <cuda_runtime.h>
#include <cuda_fp16.h>
#include <cstdint>
#include <cstddef>

#define NNODES 65536
#define NDIR   9
#define NB     (NDIR * NNODES)      // 589824 buckets: (dir, dst)
#define NTILES (NNODES / 64)        // 1024 dst tiles
#define EMAX   1048576
#define NW     (NDIR * 128 * 128)

// ---------------- scratch (static device globals; no allocation) ----------------
__device__ __align__(256) __half g_Abx[(size_t)NNODES * 128];
__device__ __align__(256) __half g_Abh[(size_t)NNODES * 128];
__device__ __align__(256) __half g_Wb1[(size_t)NW];              // blocks 0-8 = W1 dirs
__device__ __align__(256) __half g_WbB[(size_t)NW + 16384];      // block 0 = W3, blocks 1-9 = W2
__device__ __align__(16) int g_cnt[NB];
__device__ __align__(16) int g_boffs[NB + 4];
__device__ __align__(16) int g_cur[NB];
__device__ int g_part[NB / 1024];                                // 576 block partials
__device__ uint32_t g_ebuf[EMAX];    // packed: src[0:16) | dstLocal[16:22)

// ---------------- PTX helpers ----------------
__device__ __forceinline__ uint32_t smem_u32(const void* p) {
    uint32_t a;
    asm("{ .reg .u64 t; cvta.to.shared.u64 t, %1; cvt.u32.u64 %0, t; }" : "=r"(a) : "l"(p));
    return a;
}
__device__ __forceinline__ void cp_async16(uint32_t saddr, const void* gptr) {
    asm volatile("cp.async.cg.shared.global [%0], [%1], 16;" :: "r"(saddr), "l"(gptr) : "memory");
}
__device__ __forceinline__ void cp_commit() {
    asm volatile("cp.async.commit_group;" ::: "memory");
}
template <int N>
__device__ __forceinline__ void cp_wait() {
    asm volatile("cp.async.wait_group %0;" :: "n"(N) : "memory");
}
__device__ __forceinline__ void ldsm_x4(uint32_t* r, uint32_t addr) {
    asm volatile("ldmatrix.sync.aligned.m8n8.x4.shared.b16 {%0,%1,%2,%3}, [%4];"
                 : "=r"(r[0]), "=r"(r[1]), "=r"(r[2]), "=r"(r[3]) : "r"(addr));
}
__device__ __forceinline__ void mma16816(float* d, const uint32_t* a, const uint32_t* b) {
    asm volatile(
        "mma.sync.aligned.m16n8k16.row.col.f32.f16.f16.f32 "
        "{%0,%1,%2,%3}, {%4,%5,%6,%7}, {%8,%9}, {%0,%1,%2,%3};"
        : "+f"(d[0]), "+f"(d[1]), "+f"(d[2]), "+f"(d[3])
        : "r"(a[0]), "r"(a[1]), "r"(a[2]), "r"(a[3]), "r"(b[0]), "r"(b[1]));
}
__device__ __forceinline__ float elu1(float t) { return t > 0.f ? t : expm1f(t); }

// SMEM layout (1024-aligned base):
//   [0, 16K)        A tile fp16: 2 k-chunks of [64 rows x 64 halfs] swizzled
//   [16K, 80K)      B: 2 buffers x 32KB
//   [80K, 108K)     staging: 4 warps x 28 slots x 256B
//   [108K, 110K)    scale/shift tables
static constexpr int B_OFF  = 16384;
static constexpr int ST_OFF = 81920;
static constexpr int NSLOT  = 28;
static constexpr int STW    = NSLOT * 256;   // 7168 per warp
static constexpr int SC_OFF = ST_OFF + 4 * STW;   // 110592
static constexpr int SMEM_BYTES = 1024 + SC_OFF + 2048;   // 113664 -> 2 CTAs/SM

// ---------------- device building blocks ----------------
__device__ __forceinline__ void load_B(uint32_t sb, const __half* __restrict__ Wb,
                                       int wb, int p) {
    int tid = threadIdx.x;
#pragma unroll
    for (int i = 0; i < 16; i++) {
        int idx = tid + (i << 7);                // 0..2047
        int ch = idx >> 10;
        int row = (idx >> 3) & 127, g = idx & 7;
        uint32_t so = (uint32_t)(B_OFF + p * 32768 + ch * 16384 + row * 128
                                 + ((g ^ (row & 7)) << 4));
        cp_async16(sb + so, Wb + ((size_t)(wb * 128 + row)) * 128 + ch * 64 + g * 8);
    }
}

// stage this warp's contiguous edge range for bucket base bb (dir*N + tileBase)
__device__ __forceinline__ void stage_warp(uint32_t sb, const __half* __restrict__ Ab,
                                           const int* __restrict__ boffs,
                                           const uint32_t* __restrict__ ebuf,
                                           int bb, int w, int lane) {
    int s0 = __ldg(boffs + bb + 16 * w);
    int s1 = __ldg(boffs + bb + 16 * w + 16);
    int n = min(s1 - s0, NSLOT);
    uint32_t pk = 0;
    if (lane < n) pk = __ldg(ebuf + s0 + lane);
    int nseg = n << 4;                         // 16 segs of 16B per edge
    uint32_t stBase = sb + (uint32_t)(ST_OFF + w * STW);
    for (int s = lane; s < ((nseg + 31) & ~31); s += 32) {
        int slot = s >> 4;
        uint32_t p = __shfl_sync(0xFFFFFFFFu, pk, min(slot, 31));
        if (s < nseg) {
            int srcn = (int)(p & 0xFFFFu);
            cp_async16(stBase + (uint32_t)(slot * 256 + (s & 15) * 16),
                       Ab + ((size_t)srcn << 7) + (s & 15) * 8);
        }
    }
}

// accumulate this warp's 16 dst rows from staging into the swizzled fp16 A tile.
// Every row is written (zeros if no edges) -> no separate zeroing pass.
__device__ __forceinline__ void accum_warp(char* sd, const __half* __restrict__ Ab,
                                           const int* __restrict__ boffs,
                                           const uint32_t* __restrict__ ebuf,
                                           int bb, int w, int lane) {
    int rsv = __ldg(boffs + bb + 16 * w + min(lane, 16));
    int s0 = __shfl_sync(0xFFFFFFFFu, rsv, 0);
    const char* stBase = sd + ST_OFF + w * STW;
#pragma unroll 1
    for (int i = 0; i < 16; i++) {
        int r0 = __shfl_sync(0xFFFFFFFFu, rsv, i);
        int r1 = __shfl_sync(0xFFFFFFFFu, rsv, i + 1);
        float a0 = 0.f, a1 = 0.f, a2 = 0.f, a3 = 0.f;
        for (int e = r0; e < r1; e++) {
            int slot = e - s0;
            uint2 hv;
            if (slot < NSLOT) {
                hv = *reinterpret_cast<const uint2*>(stBase + slot * 256 + lane * 8);
            } else {   // rare overflow: direct global read
                uint32_t p = __ldg(ebuf + e);
                hv = __ldg(reinterpret_cast<const uint2*>(
                         Ab + ((size_t)(p & 0xFFFFu) << 7)) + lane);
            }
            __half2 h0 = *reinterpret_cast<__half2*>(&hv.x);
            __half2 h1 = *reinterpret_cast<__half2*>(&hv.y);
            float2 f0 = __half22float2(h0);
            float2 f1 = __half22float2(h1);
            a0 += f0.x; a1 += f0.y; a2 += f1.x; a3 += f1.y;
        }
        int dl = 16 * w + i;
        uint32_t fa = (uint32_t)(((lane >> 4) << 13) + dl * 128
                     + (((((lane & 15) >> 1) ^ (dl & 7)) << 4) | ((lane & 1) << 3)));
        __half2 o0 = __floats2half2_rn(a0, a1);
        __half2 o1 = __floats2half2_rn(a2, a3);
        uint2 o;
        o.x = *reinterpret_cast<uint32_t*>(&o0);
        o.y = *reinterpret_cast<uint32_t*>(&o1);
        *reinterpret_cast<uint2*>(sd + fa) = o;
    }
}

__device__ __forceinline__ void gemm_acc(uint32_t sb, float (&cfrag)[2][8][4],
                                         int p, int warpM, int warpN, int lane) {
#pragma unroll
    for (int c = 0; c < 2; c++) {
        uint32_t aBase = sb + (uint32_t)c * 8192;
        uint32_t bBase = sb + (uint32_t)(B_OFF + p * 32768 + c * 16384);
#pragma unroll
        for (int ks = 0; ks < 4; ks++) {
            uint32_t aF[2][4];
#pragma unroll
            for (int mt = 0; mt < 2; mt++) {
                int row = warpM * 32 + mt * 16 + (lane & 15);
                int g = ks * 2 + (lane >> 4);
                ldsm_x4(aF[mt], aBase + (uint32_t)row * 128 + (uint32_t)((g ^ (row & 7)) << 4));
            }
            uint32_t bF[8][2];
#pragma unroll
            for (int q = 0; q < 4; q++) {
                int n = warpN * 64 + q * 16 + ((lane >> 4) << 3) + (lane & 7);
                int g = ks * 2 + ((lane >> 3) & 1);
                uint32_t r[4];
                ldsm_x4(r, bBase + (uint32_t)n * 128 + (uint32_t)((g ^ (n & 7)) << 4));
                bF[2 * q][0] = r[0]; bF[2 * q][1] = r[1];
                bF[2 * q + 1][0] = r[2]; bF[2 * q + 1][1] = r[3];
            }
#pragma unroll
            for (int mt = 0; mt < 2; mt++)
#pragma unroll
                for (int nt = 0; nt < 8; nt++)
                    mma16816(cfrag[mt][nt], aF[mt], bF[nt]);
        }
    }
}

// ---------------- layer 1: x -> h1 (fp16), BN1+ELU fused ----------------
__global__ void __launch_bounds__(128, 2)
layer1_kernel(const __half* __restrict__ Abx, const __half* __restrict__ Wb1,
              const int* __restrict__ boffs, const uint32_t* __restrict__ ebuf,
              const float* __restrict__ b1, const float* __restrict__ g1,
              const float* __restrict__ be1, const float* __restrict__ rm1,
              const float* __restrict__ rv1,
              __half* __restrict__ Abh)
{
    extern __shared__ char smem_raw[];
    char* sd = (char*)(((uintptr_t)smem_raw + 1023) & ~(uintptr_t)1023);
    const uint32_t sb = smem_u32(sd);
    float* ssc = reinterpret_cast<float*>(sd + SC_OFF);

    const int tid = threadIdx.x;
    const int wid = tid >> 5, lane = tid & 31;
    const int warpM = wid & 1, warpN = wid >> 1;
    const int tileBase = blockIdx.x << 6;

    if (tid < 128) {
        float s = __ldg(g1 + tid) * rsqrtf(__ldg(rv1 + tid) + 1e-5f);
        ssc[tid] = s;
        ssc[128 + tid] = (__ldg(b1 + tid) - __ldg(rm1 + tid)) * s + __ldg(be1 + tid);
    }

    float cfrag[2][8][4];
#pragma unroll
    for (int mt = 0; mt < 2; mt++)
#pragma unroll
        for (int nt = 0; nt < 8; nt++)
#pragma unroll
            for (int j = 0; j < 4; j++) cfrag[mt][nt][j] = 0.f;

    // prologue: stage dir 0 edges + B0
    stage_warp(sb, Abx, boffs, ebuf, 0 * NNODES + tileBase, wid, lane);
    load_B(sb, Wb1, 0, 0);
    cp_commit();

#pragma unroll 1
    for (int d = 0; d < NDIR; d++) {
        cp_wait<0>();
        __syncthreads();     // staging_d + B_d arrived; prior MMA done (A tile free)
        accum_warp(sd, Abx, boffs, ebuf, d * NNODES + tileBase, wid, lane);
        if (d + 1 < NDIR) {
            stage_warp(sb, Abx, boffs, ebuf, (d + 1) * NNODES + tileBase, wid, lane);
            load_B(sb, Wb1, d + 1, (d + 1) & 1);
        }
        cp_commit();
        __syncthreads();     // A tile fully written
        gemm_acc(sb, cfrag, d & 1, warpM, warpN, lane);
    }

    // epilogue: h1 = fp16(ELU(y*s + sh))
#pragma unroll
    for (int mt = 0; mt < 2; mt++) {
        int r0 = tileBase + warpM * 32 + mt * 16 + (lane >> 2);
#pragma unroll
        for (int nt = 0; nt < 8; nt++) {
            int c0 = warpN * 64 + nt * 8 + ((lane & 3) << 1);
            float s0 = ssc[c0], s1 = ssc[c0 + 1];
            float h0 = ssc[128 + c0], h1 = ssc[128 + c0 + 1];
            float v00 = elu1(cfrag[mt][nt][0] * s0 + h0);
            float v01 = elu1(cfrag[mt][nt][1] * s1 + h1);
            float v10 = elu1(cfrag[mt][nt][2] * s0 + h0);
            float v11 = elu1(cfrag[mt][nt][3] * s1 + h1);
            *reinterpret_cast<__half2*>(Abh + (size_t)r0 * 128 + c0) = __floats2half2_rn(v00, v01);
            *reinterpret_cast<__half2*>(Abh + (size_t)(r0 + 8) * 128 + c0) = __floats2half2_rn(v10, v11);
        }
    }
}

// ---------------- layer 2: t=0 shortcut (W3 over x), t=1..9 W2 dirs over h1 ----------------
__global__ void __launch_bounds__(128, 2)
layer2_kernel(const __half* __restrict__ Abh, const __half* __restrict__ Abx,
              const __half* __restrict__ WbB,
              const int* __restrict__ boffs, const uint32_t* __restrict__ ebuf,
              const float* __restrict__ b2, const float* __restrict__ g2,
              const float* __restrict__ be2, const float* __restrict__ rm2,
              const float* __restrict__ rv2,
              const float* __restrict__ b3, const float* __restrict__ g3,
              const float* __restrict__ be3, const float* __restrict__ rm3,
              const float* __restrict__ rv3,
              float* __restrict__ out)
{
    extern __shared__ char smem_raw[];
    char* sd = (char*)(((uintptr_t)smem_raw + 1023) & ~(uintptr_t)1023);
    const uint32_t sb = smem_u32(sd);
    float* ssc = reinterpret_cast<float*>(sd + SC_OFF);

    const int tid = threadIdx.x;
    const int wid = tid >> 5, lane = tid & 31;
    const int warpM = wid & 1, warpN = wid >> 1;
    const int tileBase = blockIdx.x << 6;

    if (tid < 128) {
        float s2 = __ldg(g2 + tid) * rsqrtf(__ldg(rv2 + tid) + 1e-5f);
        float s3 = __ldg(g3 + tid) * rsqrtf(__ldg(rv3 + tid) + 1e-5f);
        ssc[tid]       = s2;
        ssc[128 + tid] = (__ldg(b2 + tid) - __ldg(rm2 + tid)) * s2 + __ldg(be2 + tid);
        ssc[256 + tid] = s3;
        ssc[384 + tid] = (__ldg(b3 + tid) - __ldg(rm3 + tid)) * s3 + __ldg(be3 + tid);
    }

    float cfrag[2][8][4], cfragSC[2][8][4];
#pragma unroll
    for (int mt = 0; mt < 2; mt++)
#pragma unroll
        for (int nt = 0; nt < 8; nt++)
#pragma unroll
            for (int j = 0; j < 4; j++) { cfrag[mt][nt][j] = 0.f; cfragSC[mt][nt][j] = 0.f; }

    // prologue: t=0 = shortcut (dir 0 edges over Abx), weight block 0 (W3)
    stage_warp(sb, Abx, boffs, ebuf, 0 * NNODES + tileBase, wid, lane);
    load_B(sb, WbB, 0, 0);
    cp_commit();

#pragma unroll 1
    for (int t = 0; t < 10; t++) {
        int dir = (t == 0) ? 0 : (t - 1);
        const __half* src = (t == 0) ? Abx : Abh;
        cp_wait<0>();
        __syncthreads();
        accum_warp(sd, src, boffs, ebuf, dir * NNODES + tileBase, wid, lane);
        if (t + 1 < 10) {
            int ndir = t;                       // t+1 -> dir (t+1)-1 = t
            stage_warp(sb, Abh, boffs, ebuf, ndir * NNODES + tileBase, wid, lane);
            load_B(sb, WbB, t + 1, (t + 1) & 1);
        }
        cp_commit();
        __syncthreads();
        if (t == 0) gemm_acc(sb, cfragSC, 0, warpM, warpN, lane);
        else        gemm_acc(sb, cfrag, t & 1, warpM, warpN, lane);
    }

    // epilogue: out = ELU( (ELU(y2*s2+sh2) + sc)*s3 + sh3 )
#pragma unroll
    for (int mt = 0; mt < 2; mt++) {
        int r0 = tileBase + warpM * 32 + mt * 16 + (lane >> 2);
#pragma unroll
        for (int nt = 0; nt < 8; nt++) {
            int c0 = warpN * 64 + nt * 8 + ((lane & 3) << 1);
            float s2a = ssc[c0], s2b = ssc[c0 + 1];
            float h2a = ssc[128 + c0], h2b = ssc[128 + c0 + 1];
            float s3a = ssc[256 + c0], s3b = ssc[256 + c0 + 1];
            float h3a = ssc[384 + c0], h3b = ssc[384 + c0 + 1];
            float t00 = elu1((elu1(cfrag[mt][nt][0] * s2a + h2a) + cfragSC[mt][nt][0]) * s3a + h3a);
            float t01 = elu1((elu1(cfrag[mt][nt][1] * s2b + h2b) + cfragSC[mt][nt][1]) * s3b + h3b);
            float t10 = elu1((elu1(cfrag[mt][nt][2] * s2a + h2a) + cfragSC[mt][nt][2]) * s3a + h3a);
            float t11 = elu1((elu1(cfrag[mt][nt][3] * s2b + h2b) + cfragSC[mt][nt][3]) * s3b + h3b);
            *reinterpret_cast<float2*>(out + (size_t)r0 * 128 + c0) = make_float2(t00, t01);
            *reinterpret_cast<float2*>(out + (size_t)(r0 + 8) * 128 + c0) = make_float2(t10, t11);
        }
    }
}

// ---------------- bucketing: CSR over (dir, dst) ----------------
__global__ void hist_kernel(const int* __restrict__ dst, const int* __restrict__ sel,
                            int* __restrict__ cnt, int E) {
    int i = blockIdx.x * blockDim.x + threadIdx.x;
    if (i >= E) return;
    atomicAdd(cnt + __ldg(sel + i) * NNODES + __ldg(dst + i), 1);
}

__global__ void scanA_kernel(const int* __restrict__ cnt, int* __restrict__ boffs,
                             int* __restrict__ part) {
    int t = threadIdx.x, lane = t & 31, wd = t >> 5;
    int base4 = blockIdx.x * 256 + t;
    int4 v = reinterpret_cast<const int4*>(cnt)[base4];
    int s0 = v.x, s01 = v.x + v.y, s012 = s01 + v.z, tsum = s012 + v.w;
    int inc = tsum;
#pragma unroll
    for (int off = 1; off < 32; off <<= 1) {
        int u = __shfl_up_sync(0xFFFFFFFFu, inc, off);
        if (lane >= off) inc += u;
    }
    __shared__ int wsum[8], wpf[8];
    if (lane == 31) wsum[wd] = inc;
    __syncthreads();
    if (t == 0) {
        int r = 0;
#pragma unroll
        for (int i = 0; i < 8; i++) { wpf[i] = r; r += wsum[i]; }
    }
    __syncthreads();
    int excl = wpf[wd] + inc - tsum;
    int4 o;
    o.x = excl; o.y = excl + s0; o.z = excl + s01; o.w = excl + s012;
    reinterpret_cast<int4*>(boffs)[base4] = o;
    if (t == 255) part[blockIdx.x] = excl + tsum;
}

__global__ void scanB_kernel(int* __restrict__ part, int* __restrict__ boffs_end) {
    __shared__ int a[576];
    int t = threadIdx.x;
    int orig = part[t];
    a[t] = orig;
    __syncthreads();
    for (int off = 1; off < 576; off <<= 1) {
        int v = (t >= off) ? a[t - off] : 0;
        __syncthreads();
        a[t] += v;
        __syncthreads();
    }
    part[t] = a[t] - orig;
    if (t == 575) *boffs_end = a[575];
}

__global__ void scanC_kernel(int* __restrict__ boffs, int* __restrict__ cur,
                             const int* __restrict__ part) {
    int i4 = blockIdx.x * 256 + threadIdx.x;
    int off = __ldg(part + blockIdx.x);
    int4 v = reinterpret_cast<int4*>(boffs)[i4];
    v.x += off; v.y += off; v.z += off; v.w += off;
    reinterpret_cast<int4*>(boffs)[i4] = v;
    reinterpret_cast<int4*>(cur)[i4] = v;
}

__global__ void fill_kernel(const int* __restrict__ src, const int* __restrict__ dst,
                            const int* __restrict__ sel, int* __restrict__ cur,
                            uint32_t* __restrict__ ebuf, int E) {
    int i = blockIdx.x * blockDim.x + threadIdx.x;
    if (i >= E) return;
    int dd = __ldg(dst + i);
    int b = __ldg(sel + i) * NNODES + dd;
    int p = atomicAdd(cur + b, 1);
    ebuf[p] = (uint32_t)(__ldg(src + i) & 0xFFFF) | ((uint32_t)(dd & 63) << 16);
}

// ---------------- prep kernels ----------------
__global__ void prepA_kernel(const float* __restrict__ X, __half* __restrict__ Ah) {
    int i = blockIdx.x * blockDim.x + threadIdx.x;
    if (i >= NNODES * 32) return;
    float4 x = reinterpret_cast<const float4*>(X)[i];
    reinterpret_cast<__half2*>(Ah)[i * 2] = __floats2half2_rn(x.x, x.y);
    reinterpret_cast<__half2*>(Ah)[i * 2 + 1] = __floats2half2_rn(x.z, x.w);
}

__global__ void prepW_all_kernel(const float* __restrict__ W1, const float* __restrict__ W2,
                                 const float* __restrict__ W3,
                                 __half* __restrict__ Wb1, __half* __restrict__ WbB) {
    int idx = blockIdx.x * blockDim.x + threadIdx.x;
    if (idx < NW) {
        int d = idx >> 14, k = (idx >> 7) & 127, c = idx & 127;
        Wb1[((size_t)d * 128 + c) * 128 + k] = __float2half_rn(W1[idx]);
    } else if (idx < 2 * NW) {
        int j = idx - NW;
        int d = j >> 14, k = (j >> 7) & 127, c = j & 127;
        WbB[((size_t)(1 + d) * 128 + c) * 128 + k] = __float2half_rn(W2[j]);
    } else if (idx < 2 * NW + 128 * 128) {
        int j = idx - 2 * NW;
        int k = j >> 7, c = j & 127;
        WbB[((size_t)c) * 128 + k] = __float2half_rn(W3[j]);
    }
}

// ---------------- launch ----------------
extern "C" void kernel_launch(void* const* d_in, const int* in_sizes, int n_in,
                              void* d_out, int out_size) {
    const float* x   = (const float*)d_in[0];
    const int*   ei  = (const int*)d_in[1];
    const int*   sel = (const int*)d_in[2];
    const float* W1  = (const float*)d_in[3];
    const float* b1  = (const float*)d_in[4];
    const float* g1  = (const float*)d_in[5];
    const float* be1 = (const float*)d_in[6];
    const float* rm1 = (const float*)d_in[7];
    const float* rv1 = (const float*)d_in[8];
    const float* W2  = (const float*)d_in[9];
    const float* b2  = (const float*)d_in[10];
    const float* g2  = (const float*)d_in[11];
    const float* be2 = (const float*)d_in[12];
    const float* rm2 = (const float*)d_in[13];
    const float* rv2 = (const float*)d_in[14];
    const float* W3  = (const float*)d_in[15];
    const float* b3  = (const float*)d_in[16];
    const float* g3  = (const float*)d_in[17];
    const float* be3 = (const float*)d_in[18];
    const float* rm3 = (const float*)d_in[19];
    const float* rv3 = (const float*)d_in[20];
    float* out = (float*)d_out;

    const int E = in_sizes[2];
    const int* src = ei;
    const int* dst = ei + E;

    __half *Abx, *Abh, *Wb1, *WbB;
    int *cnt, *boffs, *cur, *part;
    uint32_t* ebuf;
    cudaGetSymbolAddress((void**)&Abx, g_Abx);
    cudaGetSymbolAddress((void**)&Abh, g_Abh);
    cudaGetSymbolAddress((void**)&Wb1, g_Wb1);
    cudaGetSymbolAddress((void**)&WbB, g_WbB);
    cudaGetSymbolAddress((void**)&cnt, g_cnt);
    cudaGetSymbolAddress((void**)&boffs, g_boffs);
    cudaGetSymbolAddress((void**)&cur, g_cur);
    cudaGetSymbolAddress((void**)&part, g_part);
    cudaGetSymbolAddress((void**)&ebuf, g_ebuf);

    cudaFuncSetAttribute(layer1_kernel, cudaFuncAttributeMaxDynamicSharedMemorySize, SMEM_BYTES);
    cudaFuncSetAttribute(layer2_kernel, cudaFuncAttributeMaxDynamicSharedMemorySize, SMEM_BYTES);

    const int e_blocks = (E + 255) / 256;
    const int prepA_blocks = (NNODES * 32 + 255) / 256;
    const int prepW_blocks = (2 * NW + 128 * 128 + 255) / 256;
    const int scan_blocks = NB / 1024;   // 576

    // ---- prep + bucketing ----
    cudaMemsetAsync(cnt, 0, (size_t)NB * sizeof(int));
    prepW_all_kernel<<<prepW_blocks, 256>>>(W1, W2, W3, Wb1, WbB);
    prepA_kernel<<<prepA_blocks, 256>>>(x, Abx);
    hist_kernel<<<e_blocks, 256>>>(dst, sel, cnt, E);
    scanA_kernel<<<scan_blocks, 256>>>(cnt, boffs, part);
    scanB_kernel<<<1, 576>>>(part, boffs + NB);
    scanC_kernel<<<scan_blocks, 256>>>(boffs, cur, part);
    fill_kernel<<<e_blocks, 256>>>(src, dst, sel, cur, ebuf, E);

    // ---- layer 1: BN1+ELU fused, writes fp16 h1 ----
    layer1_kernel<<<NTILES, 128, SMEM_BYTES>>>(Abx, Wb1, boffs, ebuf,
                                               b1, g1, be1, rm1, rv1, Abh);

    // ---- layer 2: shortcut + BN2/ELU + BN3/ELU fused, writes out ----
    layer2_kernel<<<NTILES, 128, SMEM_BYTES>>>(Abh, Abx, WbB, boffs, ebuf,
                                               b2, g2, be2, rm2, rv2,
                                               b3, g3, be3, rm3, rv3, out);
}

// round 13
// speedup vs baseline: 1.5034x; 1.5034x over previous
#include <cuda_runtime.h>
#include <cuda_fp16.h>
#include <cstdint>
#include <cstddef>

#define NNODES 65536
#define NDIR   9
#define NTILES (NNODES / 64)         // 1024 tiles of 64 nodes
#define NBUCK  (NTILES * NDIR)       // 9216
#define EMAX   1048576
#define NW     (NDIR * 128 * 128)

// ---------------- scratch (static device globals; no allocation) ----------------
__device__ __align__(256) float g_acc[(size_t)NNODES * 128];
__device__ __align__(256) float g_acc3[(size_t)NNODES * 128];
__device__ __align__(256) __half g_Abx[(size_t)NNODES * 128]; // fp16 features
__device__ __align__(256) __half g_Abh[(size_t)NNODES * 128];
__device__ __align__(256) __half g_WbA[(size_t)(NDIR + 1) * 128 * 128]; // W1 dirs 0-8, W3 as dir 9
__device__ __align__(256) __half g_Wb2[(size_t)NW];
__device__ __align__(16) int g_cnt[NBUCK];
__device__ __align__(16) int g_boffs[NBUCK + 4];
__device__ __align__(16) int g_cur[NBUCK];
__device__ int g_part[16];
__device__ uint32_t g_ebuf[EMAX];    // packed: dst[0:16) | localsrc[16:22)

// ---------------- PTX helpers ----------------
__device__ __forceinline__ uint32_t smem_u32(const void* p) {
    uint32_t a;
    asm("{ .reg .u64 t; cvta.to.shared.u64 t, %1; cvt.u32.u64 %0, t; }" : "=r"(a) : "l"(p));
    return a;
}
__device__ __forceinline__ void cp_async16(uint32_t saddr, const void* gptr) {
    asm volatile("cp.async.cg.shared.global [%0], [%1], 16;" :: "r"(saddr), "l"(gptr) : "memory");
}
__device__ __forceinline__ void cp_commit() {
    asm volatile("cp.async.commit_group;" ::: "memory");
}
template <int N>
__device__ __forceinline__ void cp_wait() {
    asm volatile("cp.async.wait_group %0;" :: "n"(N) : "memory");
}
__device__ __forceinline__ void ldsm_x4(uint32_t* r, uint32_t addr) {
    asm volatile("ldmatrix.sync.aligned.m8n8.x4.shared.b16 {%0,%1,%2,%3}, [%4];"
                 : "=r"(r[0]), "=r"(r[1]), "=r"(r[2]), "=r"(r[3]) : "r"(addr));
}
__device__ __forceinline__ void mma16816(float* d, const uint32_t* a, const uint32_t* b) {
    asm volatile(
        "mma.sync.aligned.m16n8k16.row.col.f32.f16.f16.f32 "
        "{%0,%1,%2,%3}, {%4,%5,%6,%7}, {%8,%9}, {%0,%1,%2,%3};"
        : "+f"(d[0]), "+f"(d[1]), "+f"(d[2]), "+f"(d[3])
        : "r"(a[0]), "r"(a[1]), "r"(a[2]), "r"(a[3]), "r"(b[0]), "r"(b[1]));
}
__device__ __forceinline__ float elu1(float t) { return t > 0.f ? t : expm1f(t); }

// SMEM layout (dynamic, 1024-aligned base):
//   [0, 8K)   A chunk0 | [8K,16K) A chunk1 | [16K,32K) B chunk0 | [32K,48K) B chunk1
//   after mainloop, region reused as Y tile: float[64][132] (33.8KB)
static constexpr int YSTRIDE = 132;
static constexpr int SMEM_BYTES = 1024 + 49152;   // 50176 -> 4 CTAs/SM

// ---------------- fused GEMM + scatter (round-7 champion structure) ----------------
// grid = (ndirs, 1024). CTA computes Y tile [64 nodes x 128 cols] for weight block
// blockIdx.x (K=128 fp16), then scatters bucket edges into the accumulator.
// WITH_SC: blockIdx.x == NDIR means shortcut (W3): bucket dir 0, target acc3.
template <bool WITH_SC>
__global__ void __launch_bounds__(128, 4)
gemm_scatter_kernel(const __half* __restrict__ Ab,   // [N][128] fp16
                    const __half* __restrict__ Bb,   // [(ndirs)*128][128] fp16, k contiguous
                    const int* __restrict__ boffs,
                    const uint32_t* __restrict__ ebuf,
                    float* __restrict__ gacc,
                    float* __restrict__ gacc3)
{
    extern __shared__ char smem_raw[];
    char* sdata = (char*)(((uintptr_t)smem_raw + 1023) & ~(uintptr_t)1023);
    const uint32_t sb = smem_u32(sdata);

    const int tid = threadIdx.x;
    const int wid = tid >> 5, lane = tid & 31;
    const int warpM = wid & 1;        // 2 warps over M (32 rows each)
    const int warpN = wid >> 1;       // 2 warps over N (64 cols each)
    const int rowBase = blockIdx.y << 6;
    const int colBase = blockIdx.x << 7;   // weight row block
    const bool sc = WITH_SC && (blockIdx.x == NDIR);
    const int bdir = sc ? 0 : blockIdx.x;
    const int bucket = blockIdx.y * NDIR + bdir;
    float* target = sc ? gacc3 : gacc;

    float cfrag[2][8][4];
#pragma unroll
    for (int mt = 0; mt < 2; mt++)
#pragma unroll
        for (int nt = 0; nt < 8; nt++)
#pragma unroll
            for (int j = 0; j < 4; j++) cfrag[mt][nt][j] = 0.f;

    auto load_A = [&](int c) {
        uint32_t aBase = sb + (uint32_t)c * 8192;
#pragma unroll
        for (int i = 0; i < 4; i++) {
            int idx = tid + (i << 7);          // 0..511
            int row = idx >> 3, g = idx & 7;   // row 0..63, 16B group
            uint32_t so = (uint32_t)row * 128 + (uint32_t)((g ^ (row & 7)) << 4);
            cp_async16(aBase + so, Ab + (size_t)(rowBase + row) * 128 + c * 64 + g * 8);
        }
    };
    auto load_B = [&]() {
#pragma unroll
        for (int i = 0; i < 16; i++) {
            int idx = tid + (i << 7);          // 0..2047
            int ch = idx >> 10;                // chunk 0/1
            int row = (idx >> 3) & 127, g = idx & 7;
            uint32_t so = 16384u + (uint32_t)ch * 16384 + (uint32_t)row * 128
                        + (uint32_t)((g ^ (row & 7)) << 4);
            cp_async16(sb + so, Bb + (size_t)(colBase + row) * 128 + ch * 64 + g * 8);
        }
    };

    load_B();
    load_A(0);
    cp_commit();
    load_A(1);
    cp_commit();

#pragma unroll
    for (int c = 0; c < 2; c++) {
        if (c == 0) cp_wait<1>();
        else        cp_wait<0>();
        __syncthreads();

        uint32_t aBase = sb + (uint32_t)c * 8192;
        uint32_t bBase = sb + 16384u + (uint32_t)c * 16384;

#pragma unroll
        for (int ks = 0; ks < 4; ks++) {
            uint32_t aF[2][4];
#pragma unroll
            for (int mt = 0; mt < 2; mt++) {
                int row = warpM * 32 + mt * 16 + (lane & 15);
                int g = ks * 2 + (lane >> 4);
                ldsm_x4(aF[mt], aBase + (uint32_t)row * 128 + (uint32_t)((g ^ (row & 7)) << 4));
            }
            uint32_t bF[8][2];
#pragma unroll
            for (int p = 0; p < 4; p++) {
                int n = warpN * 64 + p * 16 + ((lane >> 4) << 3) + (lane & 7);
                int g = ks * 2 + ((lane >> 3) & 1);
                uint32_t r[4];
                ldsm_x4(r, bBase + (uint32_t)n * 128 + (uint32_t)((g ^ (n & 7)) << 4));
                bF[2 * p][0] = r[0]; bF[2 * p][1] = r[1];
                bF[2 * p + 1][0] = r[2]; bF[2 * p + 1][1] = r[3];
            }
#pragma unroll
            for (int mt = 0; mt < 2; mt++)
#pragma unroll
                for (int nt = 0; nt < 8; nt++)
                    mma16816(cfrag[mt][nt], aF[mt], bF[nt]);
        }
    }
    __syncthreads();   // all ldsm reads done before Y-tile overwrite

    // ---- write Y tile to SMEM (reuse pipeline region) ----
    float* yt = reinterpret_cast<float*>(sdata);
#pragma unroll
    for (int mt = 0; mt < 2; mt++) {
        int r0 = warpM * 32 + mt * 16 + (lane >> 2);
#pragma unroll
        for (int nt = 0; nt < 8; nt++) {
            int c0 = warpN * 64 + nt * 8 + ((lane & 3) << 1);
            yt[r0 * YSTRIDE + c0]       = cfrag[mt][nt][0];
            yt[r0 * YSTRIDE + c0 + 1]   = cfrag[mt][nt][1];
            yt[(r0 + 8) * YSTRIDE + c0]     = cfrag[mt][nt][2];
            yt[(r0 + 8) * YSTRIDE + c0 + 1] = cfrag[mt][nt][3];
        }
    }
    __syncthreads();

    // ---- scatter this bucket's edges (4 warps, stride 4, software-pipelined) ----
    const int e0 = __ldg(boffs + bucket);
    const int e1 = __ldg(boffs + bucket + 1);
    int e = e0 + wid;
    if (e < e1) {
        uint32_t pk = __ldg(ebuf + e);
        while (e + 4 < e1) {
            uint32_t nk = __ldg(ebuf + e + 4);   // prefetch next edge word
            int ls = (pk >> 16) & 63;
            int dst = pk & 0xFFFF;
            float4 v = *reinterpret_cast<const float4*>(yt + (size_t)ls * YSTRIDE + lane * 4);
            float* op = target + (size_t)dst * 128 + lane * 4;
            asm volatile("red.global.add.v4.f32 [%0], {%1,%2,%3,%4};"
                         :: "l"(op), "f"(v.x), "f"(v.y), "f"(v.z), "f"(v.w)
                         : "memory");
            pk = nk;
            e += 4;
        }
        int ls = (pk >> 16) & 63;
        int dst = pk & 0xFFFF;
        float4 v = *reinterpret_cast<const float4*>(yt + (size_t)ls * YSTRIDE + lane * 4);
        float* op = target + (size_t)dst * 128 + lane * 4;
        asm volatile("red.global.add.v4.f32 [%0], {%1,%2,%3,%4};"
                     :: "l"(op), "f"(v.x), "f"(v.y), "f"(v.z), "f"(v.w)
                     : "memory");
    }
}

// ---------------- edge bucketing (bucket = (srcTile64, sel)) ----------------
__global__ void hist_kernel(const int* __restrict__ src, const int* __restrict__ sel,
                            int* __restrict__ cnt, int E) {
    int i = blockIdx.x * blockDim.x + threadIdx.x;
    if (i >= E) return;
    int b = (__ldg(src + i) >> 6) * NDIR + __ldg(sel + i);
    atomicAdd(cnt + b, 1);
}

// 3-stage parallel scan over NBUCK=9216 (9 blocks x 256 threads x int4)
__global__ void scanA_kernel(const int* __restrict__ cnt, int* __restrict__ boffs,
                             int* __restrict__ part) {
    int t = threadIdx.x, lane = t & 31, wd = t >> 5;
    int base4 = blockIdx.x * 256 + t;
    int4 v = reinterpret_cast<const int4*>(cnt)[base4];
    int s0 = v.x, s01 = v.x + v.y, s012 = s01 + v.z, tsum = s012 + v.w;
    int inc = tsum;
#pragma unroll
    for (int off = 1; off < 32; off <<= 1) {
        int u = __shfl_up_sync(0xFFFFFFFFu, inc, off);
        if (lane >= off) inc += u;
    }
    __shared__ int wsum[8], wpf[8];
    if (lane == 31) wsum[wd] = inc;
    __syncthreads();
    if (t == 0) {
        int r = 0;
#pragma unroll
        for (int i = 0; i < 8; i++) { wpf[i] = r; r += wsum[i]; }
    }
    __syncthreads();
    int excl = wpf[wd] + inc - tsum;
    int4 o;
    o.x = excl; o.y = excl + s0; o.z = excl + s01; o.w = excl + s012;
    reinterpret_cast<int4*>(boffs)[base4] = o;
    if (t == 255) part[blockIdx.x] = excl + tsum;
}

__global__ void scanB_kernel(int* __restrict__ part, int* __restrict__ boffs_end) {
    if (threadIdx.x == 0) {
        int r = 0;
        for (int i = 0; i < 9; i++) { int v = part[i]; part[i] = r; r += v; }
        *boffs_end = r;
    }
}

__global__ void scanC_kernel(int* __restrict__ boffs, int* __restrict__ cur,
                             const int* __restrict__ part) {
    int i4 = blockIdx.x * 256 + threadIdx.x;
    int off = __ldg(part + blockIdx.x);
    int4 v = reinterpret_cast<int4*>(boffs)[i4];
    v.x += off; v.y += off; v.z += off; v.w += off;
    reinterpret_cast<int4*>(boffs)[i4] = v;
    reinterpret_cast<int4*>(cur)[i4] = v;
}

__global__ void fill_kernel(const int* __restrict__ src, const int* __restrict__ dst,
                            const int* __restrict__ sel, int* __restrict__ cur,
                            uint32_t* __restrict__ ebuf, int E) {
    int i = blockIdx.x * blockDim.x + threadIdx.x;
    if (i >= E) return;
    int s = __ldg(src + i);
    int b = (s >> 6) * NDIR + __ldg(sel + i);
    int p = atomicAdd(cur + b, 1);
    ebuf[p] = (uint32_t)(__ldg(dst + i) & 0xFFFF) | ((uint32_t)(s & 63) << 16);
}

// ---------------- prep kernels ----------------
__global__ void zero_both_kernel(float* __restrict__ a, float* __restrict__ b) {
    int i = blockIdx.x * blockDim.x + threadIdx.x;
    const int n4 = NNODES * 128 / 4;
    float4 z = make_float4(0.f, 0.f, 0.f, 0.f);
    if (i < n4) reinterpret_cast<float4*>(a)[i] = z;
    else if (i < 2 * n4) reinterpret_cast<float4*>(b)[i - n4] = z;
}

// X fp32 [N][128] -> fp16 [N][128]
__global__ void prepA_kernel(const float* __restrict__ X, __half* __restrict__ Ah) {
    int i = blockIdx.x * blockDim.x + threadIdx.x;
    if (i >= NNODES * 32) return;
    float4 x = reinterpret_cast<const float4*>(X)[i];
    reinterpret_cast<__half2*>(Ah)[i * 2] =
        __halves2half2(__float2half_rn(x.x), __float2half_rn(x.y));
    reinterpret_cast<__half2*>(Ah)[i * 2 + 1] =
        __halves2half2(__float2half_rn(x.z), __float2half_rn(x.w));
}

// all weights in one pass: W1 (9x128x128) -> WbA dirs 0-8; W2 -> Wb2; W3 -> WbA dir 9
__global__ void prepW_all_kernel(const float* __restrict__ W1, const float* __restrict__ W2,
                                 const float* __restrict__ W3,
                                 __half* __restrict__ WbA, __half* __restrict__ Wb2) {
    int idx = blockIdx.x * blockDim.x + threadIdx.x;
    if (idx < NW) {
        int d = idx >> 14, k = (idx >> 7) & 127, c = idx & 127;
        WbA[((size_t)d * 128 + c) * 128 + k] = __float2half_rn(W1[idx]);
    } else if (idx < 2 * NW) {
        int j = idx - NW;
        int d = j >> 14, k = (j >> 7) & 127, c = j & 127;
        Wb2[((size_t)d * 128 + c) * 128 + k] = __float2half_rn(W2[j]);
    } else if (idx < 2 * NW + 128 * 128) {
        int j = idx - 2 * NW;
        int k = j >> 7, c = j & 127;
        WbA[((size_t)NDIR * 128 + c) * 128 + k] = __float2half_rn(W3[j]);
    }
}

// ---------------- fused BN(eval) + ELU ----------------
// layer-1: acc -> fp16 features for layer 2; re-zero acc in place for reuse
__global__ void bnelu_prep_kernel(float* __restrict__ acc, const float* __restrict__ b,
                                  const float* __restrict__ g, const float* __restrict__ be,
                                  const float* __restrict__ rm, const float* __restrict__ rv,
                                  __half* __restrict__ Ah) {
    int i = blockIdx.x * blockDim.x + threadIdx.x;
    if (i >= NNODES * 128 / 4) return;
    float4 v = reinterpret_cast<const float4*>(acc)[i];
    int c0 = (i * 4) & 127;
    float o[4] = {v.x, v.y, v.z, v.w};
    float rr[4];
#pragma unroll
    for (int j = 0; j < 4; j++) {
        int c = c0 + j;
        float s = __ldg(g + c) * rsqrtf(__ldg(rv + c) + 1e-5f);
        float t = (o[j] + __ldg(b + c) - __ldg(rm + c)) * s + __ldg(be + c);
        rr[j] = elu1(t);
    }
    reinterpret_cast<__half2*>(Ah)[i * 2] =
        __halves2half2(__float2half_rn(rr[0]), __float2half_rn(rr[1]));
    reinterpret_cast<__half2*>(Ah)[i * 2 + 1] =
        __halves2half2(__float2half_rn(rr[2]), __float2half_rn(rr[3]));
    reinterpret_cast<float4*>(acc)[i] = make_float4(0.f, 0.f, 0.f, 0.f);
}

// fused layer-2 BN/ELU + shortcut combine + BN3/ELU:
// out = ELU(BN3( ELU(BN2(acc + b2)) + acc3 + b3 ))
__global__ void final2_kernel(const float* __restrict__ acc, const float* __restrict__ acc3,
                              const float* __restrict__ b2, const float* __restrict__ g2,
                              const float* __restrict__ be2, const float* __restrict__ rm2,
                              const float* __restrict__ rv2,
                              const float* __restrict__ b3, const float* __restrict__ g3,
                              const float* __restrict__ be3, const float* __restrict__ rm3,
                              const float* __restrict__ rv3,
                              float* __restrict__ out) {
    int i = blockIdx.x * blockDim.x + threadIdx.x;
    if (i >= NNODES * 128 / 4) return;
    float4 a = reinterpret_cast<const float4*>(acc)[i];
    float4 c4 = reinterpret_cast<const float4*>(acc3)[i];
    int c0 = (i * 4) & 127;
    float av[4] = {a.x, a.y, a.z, a.w};
    float sv[4] = {c4.x, c4.y, c4.z, c4.w};
    float4 r;
    float* rr = reinterpret_cast<float*>(&r);
#pragma unroll
    for (int j = 0; j < 4; j++) {
        int c = c0 + j;
        float s2 = __ldg(g2 + c) * rsqrtf(__ldg(rv2 + c) + 1e-5f);
        float h = elu1((av[j] + __ldg(b2 + c) - __ldg(rm2 + c)) * s2 + __ldg(be2 + c));
        float s3 = __ldg(g3 + c) * rsqrtf(__ldg(rv3 + c) + 1e-5f);
        float t = (h + sv[j] + __ldg(b3 + c) - __ldg(rm3 + c)) * s3 + __ldg(be3 + c);
        rr[j] = elu1(t);
    }
    reinterpret_cast<float4*>(out)[i] = r;
}

// ---------------- launch ----------------
extern "C" void kernel_launch(void* const* d_in, const int* in_sizes, int n_in,
                              void* d_out, int out_size) {
    const float* x   = (const float*)d_in[0];
    const int*   ei  = (const int*)d_in[1];
    const int*   sel = (const int*)d_in[2];
    const float* W1  = (const float*)d_in[3];
    const float* b1  = (const float*)d_in[4];
    const float* g1  = (const float*)d_in[5];
    const float* be1 = (const float*)d_in[6];
    const float* rm1 = (const float*)d_in[7];
    const float* rv1 = (const float*)d_in[8];
    const float* W2  = (const float*)d_in[9];
    const float* b2  = (const float*)d_in[10];
    const float* g2  = (const float*)d_in[11];
    const float* be2 = (const float*)d_in[12];
    const float* rm2 = (const float*)d_in[13];
    const float* rv2 = (const float*)d_in[14];
    const float* W3  = (const float*)d_in[15];
    const float* b3  = (const float*)d_in[16];
    const float* g3  = (const float*)d_in[17];
    const float* be3 = (const float*)d_in[18];
    const float* rm3 = (const float*)d_in[19];
    const float* rv3 = (const float*)d_in[20];
    float* out = (float*)d_out;

    const int E = in_sizes[2];
    const int* src = ei;
    const int* dst = ei + E;

    float *acc, *acc3;
    __half *Abx, *Abh, *WbA, *Wb2;
    int *cnt, *boffs, *cur, *part;
    uint32_t* ebuf;
    cudaGetSymbolAddress((void**)&acc, g_acc);
    cudaGetSymbolAddress((void**)&acc3, g_acc3);
    cudaGetSymbolAddress((void**)&Abx, g_Abx);
    cudaGetSymbolAddress((void**)&Abh, g_Abh);
    cudaGetSymbolAddress((void**)&WbA, g_WbA);
    cudaGetSymbolAddress((void**)&Wb2, g_Wb2);
    cudaGetSymbolAddress((void**)&cnt, g_cnt);
    cudaGetSymbolAddress((void**)&boffs, g_boffs);
    cudaGetSymbolAddress((void**)&cur, g_cur);
    cudaGetSymbolAddress((void**)&part, g_part);
    cudaGetSymbolAddress((void**)&ebuf, g_ebuf);

    cudaFuncSetAttribute(gemm_scatter_kernel<true>,
                         cudaFuncAttributeMaxDynamicSharedMemorySize, SMEM_BYTES);
    cudaFuncSetAttribute(gemm_scatter_kernel<false>,
                         cudaFuncAttributeMaxDynamicSharedMemorySize, SMEM_BYTES);

    const int nc4 = NNODES * 128 / 4;
    const int ew_blocks = (nc4 + 255) / 256;
    const int z2_blocks = (2 * nc4 + 255) / 256;
    const int prepA_blocks = (NNODES * 32 + 255) / 256;
    const int prepW_blocks = (2 * NW + 128 * 128 + 255) / 256;
    const int e_blocks = (E + 255) / 256;

    // ---- prep + bucketing ----
    cudaMemsetAsync(cnt, 0, NBUCK * sizeof(int));
    prepW_all_kernel<<<prepW_blocks, 256>>>(W1, W2, W3, WbA, Wb2);
    prepA_kernel<<<prepA_blocks, 256>>>(x, Abx);
    hist_kernel<<<e_blocks, 256>>>(src, sel, cnt, E);
    scanA_kernel<<<9, 256>>>(cnt, boffs, part);
    scanB_kernel<<<1, 32>>>(part, boffs + NBUCK);
    scanC_kernel<<<9, 256>>>(boffs, cur, part);
    fill_kernel<<<e_blocks, 256>>>(src, dst, sel, cur, ebuf, E);
    zero_both_kernel<<<z2_blocks, 256>>>(acc, acc3);

    // ---- layer 1 (9-dir) + shortcut (dir 9 = W3, sel-0 edges -> acc3) ----
    gemm_scatter_kernel<true><<<dim3(NDIR + 1, NTILES), 128, SMEM_BYTES>>>(
        Abx, WbA, boffs, ebuf, acc, acc3);
    bnelu_prep_kernel<<<ew_blocks, 256>>>(acc, b1, g1, be1, rm1, rv1, Abh);

    // ---- layer 2 (9-dir) ----
    gemm_scatter_kernel<false><<<dim3(NDIR, NTILES), 128, SMEM_BYTES>>>(
        Abh, Wb2, boffs, ebuf, acc, acc3);

    // ---- combine: ELU(BN3(ELU(BN2(acc+b2)) + acc3 + b3)) ----
    final2_kernel<<<ew_blocks, 256>>>(acc, acc3, b2, g2, be2, rm2, rv2,
                                      b3, g3, be3, rm3, rv3, out);
}